// round 15
// baseline (speedup 1.0000x reference)
#include <cuda_runtime.h>
#include <cstdint>

#define NN 100000
#define DD 64
#define EE 1600000

// Scratch (__device__ globals per allocation-free rule). Zero-initialized at load.
__device__ float g_agg [NN * DD];
__device__ float g_bufA[NN * DD];
__device__ float g_bufB[NN * DD];
__device__ int   g_deg   [NN];     // invariant: zero at kernel_launch entry
__device__ int   g_rowptr[NN + 1];
__device__ int   g_cursor[NN];
__device__ int   g_col   [EE];

typedef unsigned long long ull;
__device__ __forceinline__ ull pack2(float a, float b) {
    ull r; asm("mov.b64 %0, {%1, %2};" : "=l"(r) : "f"(a), "f"(b)); return r;
}
__device__ __forceinline__ void unpack2(ull v, float& a, float& b) {
    asm("mov.b64 {%0, %1}, %2;" : "=f"(a), "=f"(b) : "l"(v));
}
__device__ __forceinline__ ull fma2(ull a, ull b, ull c) {
    ull r; asm("fma.rn.f32x2 %0, %1, %2, %3;" : "=l"(r) : "l"(a), "l"(b), "l"(c)); return r;
}

// ---------------------------------------------------------------------------
// Launch 1: histogram of dst degrees AND copy x -> agg (block-0 self term).
// EE == NN*16, so thread e copies float4 #e and histograms edge #e.
// ---------------------------------------------------------------------------
__global__ void hist_copy_kernel(const int* __restrict__ ei,
                                 const float4* __restrict__ x4) {
    int e = blockIdx.x * blockDim.x + threadIdx.x;
    if (e < EE) {
        atomicAdd(&g_deg[ei[EE + e]], 1);
        reinterpret_cast<float4*>(g_agg)[e] = x4[e];
    }
}

// ---------------------------------------------------------------------------
// Launch 2: single-CTA scan -> rowptr, cursor
// ---------------------------------------------------------------------------
__global__ void scan_kernel() {
    __shared__ int sums[1024];
    const int CH = (NN + 1023) / 1024;
    int t = threadIdx.x;
    int base = t * CH;
    int s = 0;
    for (int i = 0; i < CH; i++) {
        int idx = base + i;
        if (idx < NN) s += g_deg[idx];
    }
    sums[t] = s;
    __syncthreads();
    for (int off = 1; off < 1024; off <<= 1) {
        int v = (t >= off) ? sums[t - off] : 0;
        __syncthreads();
        sums[t] += v;
        __syncthreads();
    }
    int prefix = (t == 0) ? 0 : sums[t - 1];
    for (int i = 0; i < CH; i++) {
        int idx = base + i;
        if (idx < NN) {
            int d = g_deg[idx];
            g_rowptr[idx] = prefix;
            g_cursor[idx] = prefix;
            prefix += d;
        }
    }
    if (t == 1023) g_rowptr[NN] = prefix;
}

// ---------------------------------------------------------------------------
// Launch 3: CSR fill + block-0 scatter aggregation + deg re-zero.
// 16 threads per edge: c = chunk index. Sub-thread 0 bumps the cursor and
// writes col; all 16 gather x[src] (coalesced float4) and red.add into
// agg[dst].
// ---------------------------------------------------------------------------
__global__ void fill_scatter_kernel(const int* __restrict__ ei,
                                    const float* __restrict__ x) {
    int t = blockIdx.x * blockDim.x + threadIdx.x;
    if (t < NN) g_deg[t] = 0;                 // restore invariant
    if (t >= EE * 16) return;
    int e = t >> 4;
    int c = t & 15;
    int s = ei[e];
    int d = ei[EE + e];
    if (c == 0) {
        int p = atomicAdd(&g_cursor[d], 1);
        g_col[p] = s;
    }
    float4 v = reinterpret_cast<const float4*>(x)[s * 16 + c];
    float4* a = reinterpret_cast<float4*>(g_agg) + d * 16 + c;
    asm volatile("red.global.add.v4.f32 [%0], {%1, %2, %3, %4};"
                 :: "l"(a), "f"(v.x), "f"(v.y), "f"(v.z), "f"(v.w)
                 : "memory");
}

// ---------------------------------------------------------------------------
// Aggregation gather (blocks 1,2): warp per dst node, two neighbor rows per
// LDG.128 warp instr. Unchanged from R11.
// ---------------------------------------------------------------------------
__global__ __launch_bounds__(256) void agg_kernel(const float* __restrict__ in,
                                                  float* __restrict__ out) {
    int w    = (blockIdx.x * blockDim.x + threadIdx.x) >> 5;
    int lane = threadIdx.x & 31;
    if (w >= NN) return;
    int half = lane >> 4;
    int c    = lane & 15;
    int start = g_rowptr[w];
    int end   = g_rowptr[w + 1];

    const float4* in4 = reinterpret_cast<const float4*>(in);
    float4 a0 = make_float4(0.f, 0.f, 0.f, 0.f);
    float4 a1 = a0, a2 = a0, a3 = a0;
    if (half == 0) a0 = in4[w * 16 + c];

    for (int i = start; i < end; i += 32) {
        int n   = min(32, end - i);
        int idx = (i + lane < end) ? g_col[i + lane] : 0;
        int j = 0;
        for (; j + 16 <= n; j += 16) {
            int s0 = __shfl_sync(0xffffffffu, idx, j      + half);
            int s1 = __shfl_sync(0xffffffffu, idx, j + 2  + half);
            int s2 = __shfl_sync(0xffffffffu, idx, j + 4  + half);
            int s3 = __shfl_sync(0xffffffffu, idx, j + 6  + half);
            int s4 = __shfl_sync(0xffffffffu, idx, j + 8  + half);
            int s5 = __shfl_sync(0xffffffffu, idx, j + 10 + half);
            int s6 = __shfl_sync(0xffffffffu, idx, j + 12 + half);
            int s7 = __shfl_sync(0xffffffffu, idx, j + 14 + half);
            float4 v0 = in4[s0 * 16 + c];
            float4 v1 = in4[s1 * 16 + c];
            float4 v2 = in4[s2 * 16 + c];
            float4 v3 = in4[s3 * 16 + c];
            float4 v4 = in4[s4 * 16 + c];
            float4 v5 = in4[s5 * 16 + c];
            float4 v6 = in4[s6 * 16 + c];
            float4 v7 = in4[s7 * 16 + c];
            a0.x += v0.x; a0.y += v0.y; a0.z += v0.z; a0.w += v0.w;
            a1.x += v1.x; a1.y += v1.y; a1.z += v1.z; a1.w += v1.w;
            a2.x += v2.x; a2.y += v2.y; a2.z += v2.z; a2.w += v2.w;
            a3.x += v3.x; a3.y += v3.y; a3.z += v3.z; a3.w += v3.w;
            a0.x += v4.x; a0.y += v4.y; a0.z += v4.z; a0.w += v4.w;
            a1.x += v5.x; a1.y += v5.y; a1.z += v5.z; a1.w += v5.w;
            a2.x += v6.x; a2.y += v6.y; a2.z += v6.z; a2.w += v6.w;
            a3.x += v7.x; a3.y += v7.y; a3.z += v7.z; a3.w += v7.w;
        }
        for (; j + 8 <= n; j += 8) {
            int s0 = __shfl_sync(0xffffffffu, idx, j     + half);
            int s1 = __shfl_sync(0xffffffffu, idx, j + 2 + half);
            int s2 = __shfl_sync(0xffffffffu, idx, j + 4 + half);
            int s3 = __shfl_sync(0xffffffffu, idx, j + 6 + half);
            float4 v0 = in4[s0 * 16 + c];
            float4 v1 = in4[s1 * 16 + c];
            float4 v2 = in4[s2 * 16 + c];
            float4 v3 = in4[s3 * 16 + c];
            a0.x += v0.x; a0.y += v0.y; a0.z += v0.z; a0.w += v0.w;
            a1.x += v1.x; a1.y += v1.y; a1.z += v1.z; a1.w += v1.w;
            a2.x += v2.x; a2.y += v2.y; a2.z += v2.z; a2.w += v2.w;
            a3.x += v3.x; a3.y += v3.y; a3.z += v3.z; a3.w += v3.w;
        }
        for (; j < n; j += 2) {
            int jj = j + half;
            int s = __shfl_sync(0xffffffffu, idx, (jj < n) ? jj : j);
            if (jj < n) {
                float4 v = in4[s * 16 + c];
                a0.x += v.x; a0.y += v.y; a0.z += v.z; a0.w += v.w;
            }
        }
    }
    a0.x += a1.x + a2.x + a3.x;  a0.y += a1.y + a2.y + a3.y;
    a0.z += a1.z + a2.z + a3.z;  a0.w += a1.w + a2.w + a3.w;
    a0.x += __shfl_xor_sync(0xffffffffu, a0.x, 16);
    a0.y += __shfl_xor_sync(0xffffffffu, a0.y, 16);
    a0.z += __shfl_xor_sync(0xffffffffu, a0.z, 16);
    a0.w += __shfl_xor_sync(0xffffffffu, a0.w, 16);
    if (half == 0)
        reinterpret_cast<float4*>(out)[w * 16 + c] = a0;
}

// ---------------------------------------------------------------------------
// MLP (unchanged from R11): 128 threads, lane owns 2 rows, STRIDE=65.
// ---------------------------------------------------------------------------
#define STRIDE 65
#define STAGE_WORDS (64 * STRIDE)

__device__ __forceinline__ void half_gemm2(const float* __restrict__ ws,
                                           const float* __restrict__ h0,
                                           const float* __restrict__ h1,
                                           ull* acc0, ull* acc1, int half) {
#pragma unroll 1
    for (int k = 0; k < DD; k++) {
        ull ha = pack2(h0[k], h0[k]);
        ull hb = pack2(h1[k], h1[k]);
#pragma unroll
        for (int jj = 0; jj < 8; jj++) {
            ulonglong2 wv = *reinterpret_cast<const ulonglong2*>(
                ws + k * DD + half * 32 + jj * 4);
            acc0[2 * jj]     = fma2(wv.x, ha, acc0[2 * jj]);
            acc0[2 * jj + 1] = fma2(wv.y, ha, acc0[2 * jj + 1]);
            acc1[2 * jj]     = fma2(wv.x, hb, acc1[2 * jj]);
            acc1[2 * jj + 1] = fma2(wv.y, hb, acc1[2 * jj + 1]);
        }
    }
}

__device__ __forceinline__ void gemm64_2(const float* ws, const ull* bu,
                                         float* h0, float* h1, bool relu) {
    ull a0[16], a1[16], b0[16], b1[16];
#pragma unroll
    for (int j = 0; j < 16; j++) { a0[j] = bu[j]; a1[j] = bu[j]; }
    half_gemm2(ws, h0, h1, a0, a1, 0);
#pragma unroll
    for (int j = 0; j < 16; j++) { b0[j] = bu[16 + j]; b1[j] = bu[16 + j]; }
    half_gemm2(ws, h0, h1, b0, b1, 1);
#pragma unroll
    for (int j = 0; j < 16; j++) {
        float p, q;
        unpack2(a0[j], p, q);
        if (relu) { p = fmaxf(p, 0.f); q = fmaxf(q, 0.f); }
        h0[2 * j] = p; h0[2 * j + 1] = q;
        unpack2(a1[j], p, q);
        if (relu) { p = fmaxf(p, 0.f); q = fmaxf(q, 0.f); }
        h1[2 * j] = p; h1[2 * j + 1] = q;
        unpack2(b0[j], p, q);
        if (relu) { p = fmaxf(p, 0.f); q = fmaxf(q, 0.f); }
        h0[32 + 2 * j] = p; h0[32 + 2 * j + 1] = q;
        unpack2(b1[j], p, q);
        if (relu) { p = fmaxf(p, 0.f); q = fmaxf(q, 0.f); }
        h1[32 + 2 * j] = p; h1[32 + 2 * j + 1] = q;
    }
}

template <int NGEMM>
__global__ __launch_bounds__(128, 2) void mlp_kernel(
        const float* __restrict__ in, float* __restrict__ out,
        const float* __restrict__ w1, const float* __restrict__ b1,
        const float* __restrict__ w2, const float* __restrict__ b2,
        const float* __restrict__ w3, const float* __restrict__ b3) {
    extern __shared__ float sm[];
    float* ws1 = sm;
    float* ws2 = sm + DD * DD;
    int tid  = threadIdx.x;
    int lane = tid & 31;
    int warp = tid >> 5;
    float* stg = sm + 2 * DD * DD + warp * STAGE_WORDS;

    for (int i = tid; i < DD * DD; i += 128) { ws1[i] = w1[i]; ws2[i] = w2[i]; }

    int rowbase = blockIdx.x * 256 + warp * 64;
#pragma unroll 4
    for (int r = 0; r < 64; r++) {
        int row = rowbase + r;
        float2 v = make_float2(0.f, 0.f);
        if (row < NN)
            v = *reinterpret_cast<const float2*>(in + (size_t)row * DD + 2 * lane);
        stg[r * STRIDE + 2 * lane]     = v.x;
        stg[r * STRIDE + 2 * lane + 1] = v.y;
    }
    __syncthreads();

    float* h0 = stg + lane * STRIDE;
    float* h1 = stg + (lane + 32) * STRIDE;

    gemm64_2(ws1, reinterpret_cast<const ull*>(b1), h0, h1, true);
    if (NGEMM >= 2)
        gemm64_2(ws2, reinterpret_cast<const ull*>(b2), h0, h1, true);
    if (NGEMM == 3) {
        __syncthreads();
        for (int i = tid; i < DD * DD; i += 128) ws1[i] = w3[i];
        __syncthreads();
        gemm64_2(ws1, reinterpret_cast<const ull*>(b3), h0, h1, false);
    }

    __syncwarp();
#pragma unroll 4
    for (int r = 0; r < 64; r++) {
        int row = rowbase + r;
        if (row < NN) {
            float2 v = make_float2(stg[r * STRIDE + 2 * lane],
                                   stg[r * STRIDE + 2 * lane + 1]);
            *reinterpret_cast<float2*>(out + (size_t)row * DD + 2 * lane) = v;
        }
    }
}

// ---------------------------------------------------------------------------
// Launch. ncu window = launch #4 == first mlp_kernel<2>.
// ---------------------------------------------------------------------------
extern "C" void kernel_launch(void* const* d_in, const int* in_sizes, int n_in,
                              void* d_out, int out_size) {
    const float* x  = (const float*)d_in[0];
    const int*   ei = (const int*)d_in[1];
    const float* w1[3] = {(const float*)d_in[2], (const float*)d_in[6],  (const float*)d_in[10]};
    const float* b1[3] = {(const float*)d_in[3], (const float*)d_in[7],  (const float*)d_in[11]};
    const float* w2[3] = {(const float*)d_in[4], (const float*)d_in[8],  (const float*)d_in[12]};
    const float* b2[3] = {(const float*)d_in[5], (const float*)d_in[9],  (const float*)d_in[13]};
    const float* wf = (const float*)d_in[14];
    const float* bf = (const float*)d_in[15];
    float* out = (float*)d_out;

    float *agg, *bufA, *bufB;
    cudaGetSymbolAddress((void**)&agg,  g_agg);
    cudaGetSymbolAddress((void**)&bufA, g_bufA);
    cudaGetSymbolAddress((void**)&bufB, g_bufB);

    const int SMEM = (2 * DD * DD + 4 * STAGE_WORDS) * 4;   // 99.3 KB
    static bool attr_done = false;
    if (!attr_done) {
        cudaFuncSetAttribute(mlp_kernel<2>,
                             cudaFuncAttributeMaxDynamicSharedMemorySize, SMEM);
        cudaFuncSetAttribute(mlp_kernel<3>,
                             cudaFuncAttributeMaxDynamicSharedMemorySize, SMEM);
        attr_done = true;
    }

    const int AGG_GRID = (NN * 32 + 255) / 256;
    const int MLP_GRID = (NN + 255) / 256;

    // #1: hist + copy x->agg
    hist_copy_kernel<<<(EE + 511) / 512, 512>>>(ei, (const float4*)x);
    // #2: scan
    scan_kernel<<<1, 1024>>>();
    // #3: CSR fill + block-0 scatter aggregation + deg re-zero
    fill_scatter_kernel<<<(EE * 16 + 511) / 512, 512>>>(ei, x);
    // #4: block-0 MLP  <-- ncu capture lands here
    mlp_kernel<2><<<MLP_GRID, 128, SMEM>>>(agg, bufA, w1[0], b1[0], w2[0], b2[0], nullptr, nullptr);
    // block 1
    agg_kernel<<<AGG_GRID, 256>>>(bufA, agg);
    mlp_kernel<2><<<MLP_GRID, 128, SMEM>>>(agg, bufB, w1[1], b1[1], w2[1], b2[1], nullptr, nullptr);
    // block 2 + final linear (fused)
    agg_kernel<<<AGG_GRID, 256>>>(bufB, agg);
    mlp_kernel<3><<<MLP_GRID, 128, SMEM>>>(agg, out, w1[2], b1[2], w2[2], b2[2], wf, bf);
}

// round 16
// speedup vs baseline: 1.0803x; 1.0803x over previous
#include <cuda_runtime.h>
#include <cstdint>

#define NN 100000
#define DD 64
#define EE 1600000

// Scratch (__device__ globals per allocation-free rule). Zero-initialized at load.
__device__ float g_agg [NN * DD];
__device__ float g_bufA[NN * DD];
__device__ float g_bufB[NN * DD];
__device__ int   g_deg   [NN];     // invariant: zero at kernel_launch entry
__device__ int   g_rowptr[NN + 1];
__device__ int   g_cursor[NN];
__device__ int   g_col   [EE];

typedef unsigned long long ull;
__device__ __forceinline__ ull pack2(float a, float b) {
    ull r; asm("mov.b64 %0, {%1, %2};" : "=l"(r) : "f"(a), "f"(b)); return r;
}
__device__ __forceinline__ void unpack2(ull v, float& a, float& b) {
    asm("mov.b64 {%0, %1}, %2;" : "=f"(a), "=f"(b) : "l"(v));
}
__device__ __forceinline__ ull fma2(ull a, ull b, ull c) {
    ull r; asm("fma.rn.f32x2 %0, %1, %2, %3;" : "=l"(r) : "l"(a), "l"(b), "l"(c)); return r;
}

// ---------------------------------------------------------------------------
// CSR build (3 launches; deg re-zeroed by fill for the NEXT launch)
// ---------------------------------------------------------------------------
__global__ void hist_kernel(const int* __restrict__ ei) {
    int e = blockIdx.x * blockDim.x + threadIdx.x;
    if (e < EE) atomicAdd(&g_deg[ei[EE + e]], 1);
}

__global__ void scan_kernel() {
    __shared__ int sums[1024];
    const int CH = (NN + 1023) / 1024;
    int t = threadIdx.x;
    int base = t * CH;
    int s = 0;
    for (int i = 0; i < CH; i++) {
        int idx = base + i;
        if (idx < NN) s += g_deg[idx];
    }
    sums[t] = s;
    __syncthreads();
    for (int off = 1; off < 1024; off <<= 1) {
        int v = (t >= off) ? sums[t - off] : 0;
        __syncthreads();
        sums[t] += v;
        __syncthreads();
    }
    int prefix = (t == 0) ? 0 : sums[t - 1];
    for (int i = 0; i < CH; i++) {
        int idx = base + i;
        if (idx < NN) {
            int d = g_deg[idx];
            g_rowptr[idx] = prefix;
            g_cursor[idx] = prefix;
            prefix += d;
        }
    }
    if (t == 1023) g_rowptr[NN] = prefix;
}

__global__ void fill_kernel(const int* __restrict__ ei) {
    int e = blockIdx.x * blockDim.x + threadIdx.x;
    if (e < EE) {
        int d = ei[EE + e];
        int p = atomicAdd(&g_cursor[d], 1);
        g_col[p] = ei[e];
    }
    if (e < NN) g_deg[e] = 0;   // restore invariant for next launch
}

// ---------------------------------------------------------------------------
// Aggregation gather: warp per dst node, two neighbor rows per LDG.128 warp
// instr (lanes 0-15 neighbor j, lanes 16-31 neighbor j+1).
// ---------------------------------------------------------------------------
__global__ __launch_bounds__(256) void agg_kernel(const float* __restrict__ in,
                                                  float* __restrict__ out) {
    int w    = (blockIdx.x * blockDim.x + threadIdx.x) >> 5;
    int lane = threadIdx.x & 31;
    if (w >= NN) return;
    int half = lane >> 4;
    int c    = lane & 15;
    int start = g_rowptr[w];
    int end   = g_rowptr[w + 1];

    const float4* in4 = reinterpret_cast<const float4*>(in);
    float4 a0 = make_float4(0.f, 0.f, 0.f, 0.f);
    float4 a1 = a0, a2 = a0, a3 = a0;
    if (half == 0) a0 = in4[(size_t)w * 16 + c];

    for (int i = start; i < end; i += 32) {
        int n   = min(32, end - i);
        int idx = (i + lane < end) ? g_col[i + lane] : 0;
        int j = 0;
        for (; j + 16 <= n; j += 16) {
            int s0 = __shfl_sync(0xffffffffu, idx, j      + half);
            int s1 = __shfl_sync(0xffffffffu, idx, j + 2  + half);
            int s2 = __shfl_sync(0xffffffffu, idx, j + 4  + half);
            int s3 = __shfl_sync(0xffffffffu, idx, j + 6  + half);
            int s4 = __shfl_sync(0xffffffffu, idx, j + 8  + half);
            int s5 = __shfl_sync(0xffffffffu, idx, j + 10 + half);
            int s6 = __shfl_sync(0xffffffffu, idx, j + 12 + half);
            int s7 = __shfl_sync(0xffffffffu, idx, j + 14 + half);
            float4 v0 = in4[(size_t)s0 * 16 + c];
            float4 v1 = in4[(size_t)s1 * 16 + c];
            float4 v2 = in4[(size_t)s2 * 16 + c];
            float4 v3 = in4[(size_t)s3 * 16 + c];
            float4 v4 = in4[(size_t)s4 * 16 + c];
            float4 v5 = in4[(size_t)s5 * 16 + c];
            float4 v6 = in4[(size_t)s6 * 16 + c];
            float4 v7 = in4[(size_t)s7 * 16 + c];
            a0.x += v0.x; a0.y += v0.y; a0.z += v0.z; a0.w += v0.w;
            a1.x += v1.x; a1.y += v1.y; a1.z += v1.z; a1.w += v1.w;
            a2.x += v2.x; a2.y += v2.y; a2.z += v2.z; a2.w += v2.w;
            a3.x += v3.x; a3.y += v3.y; a3.z += v3.z; a3.w += v3.w;
            a0.x += v4.x; a0.y += v4.y; a0.z += v4.z; a0.w += v4.w;
            a1.x += v5.x; a1.y += v5.y; a1.z += v5.z; a1.w += v5.w;
            a2.x += v6.x; a2.y += v6.y; a2.z += v6.z; a2.w += v6.w;
            a3.x += v7.x; a3.y += v7.y; a3.z += v7.z; a3.w += v7.w;
        }
        for (; j + 8 <= n; j += 8) {
            int s0 = __shfl_sync(0xffffffffu, idx, j     + half);
            int s1 = __shfl_sync(0xffffffffu, idx, j + 2 + half);
            int s2 = __shfl_sync(0xffffffffu, idx, j + 4 + half);
            int s3 = __shfl_sync(0xffffffffu, idx, j + 6 + half);
            float4 v0 = in4[(size_t)s0 * 16 + c];
            float4 v1 = in4[(size_t)s1 * 16 + c];
            float4 v2 = in4[(size_t)s2 * 16 + c];
            float4 v3 = in4[(size_t)s3 * 16 + c];
            a0.x += v0.x; a0.y += v0.y; a0.z += v0.z; a0.w += v0.w;
            a1.x += v1.x; a1.y += v1.y; a1.z += v1.z; a1.w += v1.w;
            a2.x += v2.x; a2.y += v2.y; a2.z += v2.z; a2.w += v2.w;
            a3.x += v3.x; a3.y += v3.y; a3.z += v3.z; a3.w += v3.w;
        }
        for (; j < n; j += 2) {
            int jj = j + half;
            int s = __shfl_sync(0xffffffffu, idx, (jj < n) ? jj : j);
            if (jj < n) {
                float4 v = in4[(size_t)s * 16 + c];
                a0.x += v.x; a0.y += v.y; a0.z += v.z; a0.w += v.w;
            }
        }
    }
    a0.x += a1.x + a2.x + a3.x;  a0.y += a1.y + a2.y + a3.y;
    a0.z += a1.z + a2.z + a3.z;  a0.w += a1.w + a2.w + a3.w;
    a0.x += __shfl_xor_sync(0xffffffffu, a0.x, 16);
    a0.y += __shfl_xor_sync(0xffffffffu, a0.y, 16);
    a0.z += __shfl_xor_sync(0xffffffffu, a0.z, 16);
    a0.w += __shfl_xor_sync(0xffffffffu, a0.w, 16);
    if (half == 0)
        reinterpret_cast<float4*>(out)[(size_t)w * 16 + c] = a0;
}

// ---------------------------------------------------------------------------
// MLP: OCCUPANCY-FIRST. 128 threads (4 warps), 1 row per lane, 32 rows/warp
// staged in smem (STRIDE 65 => conflict-free own-row access). Single shared
// 64x64 weight buffer, reloaded between GEMMs. acc held as 2x16 ull halves.
// smem 49.7KB, ~116 regs -> 4 CTAs/SM = 16 warps/SM (vs 8 before).
// ---------------------------------------------------------------------------
#define STRIDE 65
#define RPW 32                       // rows per warp
#define MLP_SMEM_WORDS (DD * DD + 4 * RPW * STRIDE)   // 4096 + 8320 = 12416

__device__ __forceinline__ void gemm64_1(const float* __restrict__ ws,
                                         const ull* __restrict__ bu,
                                         float* __restrict__ h, bool relu) {
    ull a[16], b[16];
#pragma unroll
    for (int j = 0; j < 16; j++) a[j] = bu[j];
#pragma unroll 1
    for (int k = 0; k < DD; k++) {
        float hk = h[k];
        ull h2 = pack2(hk, hk);
#pragma unroll
        for (int jj = 0; jj < 8; jj++) {
            ulonglong2 wv = *reinterpret_cast<const ulonglong2*>(ws + k * DD + jj * 4);
            a[2 * jj]     = fma2(wv.x, h2, a[2 * jj]);
            a[2 * jj + 1] = fma2(wv.y, h2, a[2 * jj + 1]);
        }
    }
#pragma unroll
    for (int j = 0; j < 16; j++) b[j] = bu[16 + j];
#pragma unroll 1
    for (int k = 0; k < DD; k++) {
        float hk = h[k];
        ull h2 = pack2(hk, hk);
#pragma unroll
        for (int jj = 0; jj < 8; jj++) {
            ulonglong2 wv = *reinterpret_cast<const ulonglong2*>(ws + k * DD + 32 + jj * 4);
            b[2 * jj]     = fma2(wv.x, h2, b[2 * jj]);
            b[2 * jj + 1] = fma2(wv.y, h2, b[2 * jj + 1]);
        }
    }
    // write back AFTER both halves consumed h (lane-private row)
#pragma unroll
    for (int j = 0; j < 16; j++) {
        float p, q;
        unpack2(a[j], p, q);
        if (relu) { p = fmaxf(p, 0.f); q = fmaxf(q, 0.f); }
        h[2 * j] = p; h[2 * j + 1] = q;
        unpack2(b[j], p, q);
        if (relu) { p = fmaxf(p, 0.f); q = fmaxf(q, 0.f); }
        h[32 + 2 * j] = p; h[32 + 2 * j + 1] = q;
    }
}

template <int NGEMM>
__global__ __launch_bounds__(128, 4) void mlp_kernel(
        const float* __restrict__ in, float* __restrict__ out,
        const float* __restrict__ w1, const float* __restrict__ b1,
        const float* __restrict__ w2, const float* __restrict__ b2,
        const float* __restrict__ w3, const float* __restrict__ b3) {
    extern __shared__ float sm[];
    float* ws = sm;
    int tid  = threadIdx.x;
    int lane = tid & 31;
    int warp = tid >> 5;
    float* stg = sm + DD * DD + warp * RPW * STRIDE;

    for (int i = tid; i < DD * DD; i += 128) ws[i] = w1[i];

    int rowbase = blockIdx.x * 128 + warp * RPW;
#pragma unroll 4
    for (int r = 0; r < RPW; r++) {
        int row = rowbase + r;
        float2 v = make_float2(0.f, 0.f);
        if (row < NN)
            v = *reinterpret_cast<const float2*>(in + (size_t)row * DD + 2 * lane);
        stg[r * STRIDE + 2 * lane]     = v.x;
        stg[r * STRIDE + 2 * lane + 1] = v.y;
    }
    __syncthreads();

    float* h = stg + lane * STRIDE;        // this lane's row

    gemm64_1(ws, reinterpret_cast<const ull*>(b1), h, true);
    __syncthreads();                       // all warps done reading w1
    for (int i = tid; i < DD * DD; i += 128) ws[i] = w2[i];
    __syncthreads();
    gemm64_1(ws, reinterpret_cast<const ull*>(b2), h, true);
    if (NGEMM == 3) {
        __syncthreads();
        for (int i = tid; i < DD * DD; i += 128) ws[i] = w3[i];
        __syncthreads();
        gemm64_1(ws, reinterpret_cast<const ull*>(b3), h, false);
    }

    __syncwarp();                          // own-warp rows written by lanes
#pragma unroll 4
    for (int r = 0; r < RPW; r++) {
        int row = rowbase + r;
        if (row < NN) {
            float2 v = make_float2(stg[r * STRIDE + 2 * lane],
                                   stg[r * STRIDE + 2 * lane + 1]);
            *reinterpret_cast<float2*>(out + (size_t)row * DD + 2 * lane) = v;
        }
    }
}

// ---------------------------------------------------------------------------
// Launch
// ---------------------------------------------------------------------------
extern "C" void kernel_launch(void* const* d_in, const int* in_sizes, int n_in,
                              void* d_out, int out_size) {
    const float* x  = (const float*)d_in[0];
    const int*   ei = (const int*)d_in[1];
    const float* w1[3] = {(const float*)d_in[2], (const float*)d_in[6],  (const float*)d_in[10]};
    const float* b1[3] = {(const float*)d_in[3], (const float*)d_in[7],  (const float*)d_in[11]};
    const float* w2[3] = {(const float*)d_in[4], (const float*)d_in[8],  (const float*)d_in[12]};
    const float* b2[3] = {(const float*)d_in[5], (const float*)d_in[9],  (const float*)d_in[13]};
    const float* wf = (const float*)d_in[14];
    const float* bf = (const float*)d_in[15];
    float* out = (float*)d_out;

    float *agg, *bufA, *bufB;
    cudaGetSymbolAddress((void**)&agg,  g_agg);
    cudaGetSymbolAddress((void**)&bufA, g_bufA);
    cudaGetSymbolAddress((void**)&bufB, g_bufB);

    const int SMEM = MLP_SMEM_WORDS * 4;   // 49,664 B
    static bool attr_done = false;
    if (!attr_done) {
        cudaFuncSetAttribute(mlp_kernel<2>,
                             cudaFuncAttributeMaxDynamicSharedMemorySize, SMEM);
        cudaFuncSetAttribute(mlp_kernel<3>,
                             cudaFuncAttributeMaxDynamicSharedMemorySize, SMEM);
        attr_done = true;
    }

    const int EDGE_GRID = (EE + 511) / 512;
    const int AGG_GRID  = (NN * 32 + 255) / 256;
    const int MLP_GRID  = (NN + 127) / 128;   // 782 CTAs, 128 rows each

    // CSR build
    hist_kernel<<<EDGE_GRID, 512>>>(ei);
    scan_kernel<<<1, 1024>>>();
    fill_kernel<<<EDGE_GRID, 512>>>(ei);

    // block 0
    agg_kernel<<<AGG_GRID, 256>>>(x, agg);
    mlp_kernel<2><<<MLP_GRID, 128, SMEM>>>(agg, bufA, w1[0], b1[0], w2[0], b2[0], nullptr, nullptr);
    // block 1
    agg_kernel<<<AGG_GRID, 256>>>(bufA, agg);
    mlp_kernel<2><<<MLP_GRID, 128, SMEM>>>(agg, bufB, w1[1], b1[1], w2[1], b2[1], nullptr, nullptr);
    // block 2 + final linear (fused)
    agg_kernel<<<AGG_GRID, 256>>>(bufB, agg);
    mlp_kernel<3><<<MLP_GRID, 128, SMEM>>>(agg, out, w1[2], b1[2], w2[2], b2[2], wf, bf);
}